// round 12
// baseline (speedup 1.0000x reference)
#include <cuda_runtime.h>
#include <cuda_fp16.h>

// Problem: B=1, H=W=D=128.
// dti: (6,128,128,128) f32 ; ddf: (3,128,128,128) f32 ; out: (6,128,128,128) f32
#define NV (128*128*128)

// fp16 interleaved gather array, padded to 16B/voxel (32MB):
//   g_t[v] = { h(c0,c1), h(c2,c3), h(c4,c5), 0 }
__device__ uint4 g_t[NV];

typedef unsigned long long u64;

__device__ __forceinline__ float frcp_a(float x)  { float r; asm("rcp.approx.f32 %0, %1;"   : "=f"(r) : "f"(x)); return r; }
__device__ __forceinline__ float fsqrt_a(float x) { float r; asm("sqrt.approx.f32 %0, %1;"  : "=f"(r) : "f"(x)); return r; }
__device__ __forceinline__ float frsqrt_a(float x){ float r; asm("rsqrt.approx.f32 %0, %1;" : "=f"(r) : "f"(x)); return r; }

// ---- packed f32x2 helpers (lane0 = low 32 bits = voxel A) ----
__device__ __forceinline__ u64 pk(float lo, float hi) {
    u64 r; asm("mov.b64 %0, {%1,%2};" : "=l"(r) : "f"(lo), "f"(hi)); return r;
}
__device__ __forceinline__ void upk(u64 v, float& lo, float& hi) {
    asm("mov.b64 {%0,%1}, %2;" : "=f"(lo), "=f"(hi) : "l"(v));
}
__device__ __forceinline__ u64 f2mul(u64 a, u64 b) {
    u64 r; asm("mul.rn.f32x2 %0, %1, %2;" : "=l"(r) : "l"(a), "l"(b)); return r;
}
__device__ __forceinline__ u64 f2add(u64 a, u64 b) {
    u64 r; asm("add.rn.f32x2 %0, %1, %2;" : "=l"(r) : "l"(a), "l"(b)); return r;
}
__device__ __forceinline__ u64 f2fma(u64 a, u64 b, u64 c) {
    u64 r; asm("fma.rn.f32x2 %0, %1, %2, %3;" : "=l"(r) : "l"(a), "l"(b), "l"(c)); return r;
}
#define KNEG1 0xBF800000BF800000ULL
#define KONE  0x3F8000003F800000ULL
__device__ __forceinline__ u64 f2sub(u64 a, u64 b) { return f2fma(b, (u64)KNEG1, a); }

__device__ __forceinline__ unsigned pack2h(float a, float b) {
    __half2 h = __floats2half2_rn(a, b);
    return *(unsigned*)&h;
}

// -------- pre-pass: planar fp32 (6,NV) -> interleaved fp16 uint4 (NV) -------
// 4 voxels per thread: 6x LDG.128 in, 4x STG.128 out, fully coalesced.
__global__ __launch_bounds__(256)
void convert_kernel(const float4* __restrict__ src4)
{
    const int j = blockIdx.x * 256 + threadIdx.x;    // [0, NV/4)
    const int Q = NV / 4;
    float4 c0 = src4[j];
    float4 c1 = src4[Q + j];
    float4 c2 = src4[2 * Q + j];
    float4 c3 = src4[3 * Q + j];
    float4 c4 = src4[4 * Q + j];
    float4 c5 = src4[5 * Q + j];
    uint4 t0, t1, t2, t3;
    t0.x = pack2h(c0.x, c1.x); t0.y = pack2h(c2.x, c3.x); t0.z = pack2h(c4.x, c5.x); t0.w = 0;
    t1.x = pack2h(c0.y, c1.y); t1.y = pack2h(c2.y, c3.y); t1.z = pack2h(c4.y, c5.y); t1.w = 0;
    t2.x = pack2h(c0.z, c1.z); t2.y = pack2h(c2.z, c3.z); t2.z = pack2h(c4.z, c5.z); t2.w = 0;
    t3.x = pack2h(c0.w, c1.w); t3.y = pack2h(c2.w, c3.w); t3.z = pack2h(c4.w, c5.w); t3.w = 0;
    g_t[4 * j]     = t0;
    g_t[4 * j + 1] = t1;
    g_t[4 * j + 2] = t2;
    g_t[4 * j + 3] = t3;
}

// corner-setup result for one voxel
struct GSetup {
    int i000, edx, edy, edz;
    float w[4];
    __half2 fzh;
};

__device__ __forceinline__ GSetup gsetup(float cxv, float cyv, float czv)
{
    GSetup s;
    float x0f = floorf(cxv), y0f = floorf(cyv), z0f = floorf(czv);
    float fx = cxv - x0f, fy = cyv - y0f, fz = czv - z0f;
    int x0 = (int)x0f, y0 = (int)y0f, z0 = (int)z0f;
    s.edx = (x0 < 127 ? 1 : 0) << 14;
    s.edy = (y0 < 127 ? 1 : 0) << 7;
    s.edz = (z0 < 127 ? 1 : 0);
    s.i000 = (x0 << 14) | (y0 << 7) | z0;
    s.fzh = __float2half2_rn(fz);
    const float gx0 = 1.0f - fx, gy0 = 1.0f - fy;
    s.w[0] = gx0 * gy0; s.w[1] = gx0 * fy; s.w[2] = fx * gy0; s.w[3] = fx * fy;
    return s;
}

__global__ __launch_bounds__(256, 4)
void warp_dti_kernel(const float* __restrict__ ddf,
                     float* __restrict__ out)
{
    const int t = blockIdx.x * 256 + threadIdx.x;   // NV/2 threads
    const int v = t << 1;                           // voxel pair (v, v+1)
    const int z = v & 127;                          // even, 0..126
    const int y = (v >> 7) & 127;
    const int x = v >> 14;

    // ---------------- center ddf for both voxels (packed LDG.64) ------------
    const u64 d0 = *(const u64*)(ddf + v);
    const u64 d1 = *(const u64*)(ddf + NV + v);
    const u64 d2 = *(const u64*)(ddf + 2 * NV + v);
    float dxA, dxB, dyA, dyB, dzA, dzB;
    upk(d0, dxA, dxB); upk(d1, dyA, dyB); upk(d2, dzA, dzB);

    // ---------------- trilinear gather, both voxels interleaved -------------
    GSetup sA = gsetup(fminf(fmaxf((float)x + dxA, 0.0f), 127.0f),
                       fminf(fmaxf((float)y + dyA, 0.0f), 127.0f),
                       fminf(fmaxf((float)z + dzA, 0.0f), 127.0f));
    GSetup sB = gsetup(fminf(fmaxf((float)x + dxB, 0.0f), 127.0f),
                       fminf(fmaxf((float)y + dyB, 0.0f), 127.0f),
                       fminf(fmaxf((float)(z + 1) + dzB, 0.0f), 127.0f));

    u64 a01 = 0, a23 = 0, a45 = 0;       // voxel A accumulators (channel pairs)
    u64 b01 = 0, b23 = 0, b45 = 0;       // voxel B
    #pragma unroll
    for (int k = 0; k < 4; k++) {
        const int iA = sA.i000 + ((k & 1) ? sA.edy : 0) + ((k & 2) ? sA.edx : 0);
        const int iB = sB.i000 + ((k & 1) ? sB.edy : 0) + ((k & 2) ? sB.edx : 0);
        // 4 independent LDG.128s
        const uint4 A0 = g_t[iA];
        const uint4 A1 = g_t[iA + sA.edz];
        const uint4 B0 = g_t[iB];
        const uint4 B1 = g_t[iB + sB.edz];

        const u64 wA = pk(sA.w[k], sA.w[k]);
        const u64 wB = pk(sB.w[k], sB.w[k]);

        __half2 p0 = *(const __half2*)&A0.x, q0 = *(const __half2*)&A1.x;
        __half2 p1 = *(const __half2*)&A0.y, q1 = *(const __half2*)&A1.y;
        __half2 p2 = *(const __half2*)&A0.z, q2 = *(const __half2*)&A1.z;
        float2 lA0 = __half22float2(__hfma2(sA.fzh, __hsub2(q0, p0), p0));
        float2 lA1 = __half22float2(__hfma2(sA.fzh, __hsub2(q1, p1), p1));
        float2 lA2 = __half22float2(__hfma2(sA.fzh, __hsub2(q2, p2), p2));
        a01 = f2fma(wA, pk(lA0.x, lA0.y), a01);
        a23 = f2fma(wA, pk(lA1.x, lA1.y), a23);
        a45 = f2fma(wA, pk(lA2.x, lA2.y), a45);

        __half2 r0 = *(const __half2*)&B0.x, s0 = *(const __half2*)&B1.x;
        __half2 r1 = *(const __half2*)&B0.y, s1 = *(const __half2*)&B1.y;
        __half2 r2 = *(const __half2*)&B0.z, s2 = *(const __half2*)&B1.z;
        float2 lB0 = __half22float2(__hfma2(sB.fzh, __hsub2(s0, r0), r0));
        float2 lB1 = __half22float2(__hfma2(sB.fzh, __hsub2(s1, r1), r1));
        float2 lB2 = __half22float2(__hfma2(sB.fzh, __hsub2(s2, r2), r2));
        b01 = f2fma(wB, pk(lB0.x, lB0.y), b01);
        b23 = f2fma(wB, pk(lB1.x, lB1.y), b23);
        b45 = f2fma(wB, pk(lB2.x, lB2.y), b45);
    }

    // repack channel-pairs -> voxel-pair M entries
    float m0A, m1A, m2A, m3A, m4A, m5A, m0B, m1B, m2B, m3B, m4B, m5B;
    upk(a01, m0A, m1A); upk(a23, m2A, m3A); upk(a45, m4A, m5A);
    upk(b01, m0B, m1B); upk(b23, m2B, m3B); upk(b45, m4B, m5B);
    const u64 M00 = pk(m0A, m0B), M01 = pk(m1A, m1B), M11 = pk(m2A, m2B);
    const u64 M02 = pk(m3A, m3B), M12 = pk(m4A, m4B), M22 = pk(m5A, m5B);

    // ---------------- Jacobian (packed over the voxel pair) -----------------
    const int xp = min(x + 1, 127), xm = max(x - 1, 0);
    const int yp = min(y + 1, 127), ym = max(y - 1, 0);
    const float sxs = 1.5f - 0.5f * (float)(xp - xm);
    const float sys = 1.5f - 0.5f * (float)(yp - ym);
    const float szA = (z == 0)   ? 1.0f : 0.5f;   // voxel A at z (z even)
    const float szB = (z == 126) ? 1.0f : 0.5f;   // voxel B at z+1
    const u64 sx2 = pk(sxs, sxs), sy2 = pk(sys, sys), sz2 = pk(szA, szB);

    const int rowb = (x << 14) | (y << 7);
    const int ixp = (xp << 14) | (y << 7) | z;
    const int ixm = (xm << 14) | (y << 7) | z;
    const int iyp = (x << 14) | (yp << 7) | z;
    const int iym = (x << 14) | (ym << 7) | z;
    const int izm = rowb + max(z - 1, 0);
    const int izp = rowb + min(z + 2, 127);

    u64 X00, X01, X02, X10, X11, X12, X20, X21, X22;
    {
        const u64 cen[3] = { d0, d1, d2 };
        u64 Xr[3][3];
        #pragma unroll
        for (int i = 0; i < 3; i++) {
            const float* p = ddf + i * NV;
            u64 pxp = *(const u64*)(p + ixp);
            u64 pxm = *(const u64*)(p + ixm);
            u64 pyp = *(const u64*)(p + iyp);
            u64 pym = *(const u64*)(p + iym);
            float pzm = p[izm], pzp = p[izp];
            float cl, ch; upk(cen[i], cl, ch);
            Xr[i][0] = f2mul(f2sub(pxp, pxm), sx2);
            Xr[i][1] = f2mul(f2sub(pyp, pym), sy2);
            Xr[i][2] = f2mul(f2sub(pk(ch, pzp), pk(pzm, cl)), sz2);
        }
        X00 = f2add(Xr[0][0], (u64)KONE); X01 = Xr[0][1]; X02 = Xr[0][2];
        X10 = Xr[1][0]; X11 = f2add(Xr[1][1], (u64)KONE); X12 = Xr[1][2];
        X20 = Xr[2][0]; X21 = Xr[2][1]; X22 = f2add(Xr[2][2], (u64)KONE);
    }

    // ---------------- polar factor: packed Newton (2 scaled + 2 plain) ------
    #pragma unroll
    for (int it = 0; it < 4; it++) {
        u64 C00 = f2sub(f2mul(X11, X22), f2mul(X12, X21));
        u64 C01 = f2sub(f2mul(X12, X20), f2mul(X10, X22));
        u64 C02 = f2sub(f2mul(X10, X21), f2mul(X11, X20));
        u64 C10 = f2sub(f2mul(X02, X21), f2mul(X01, X22));
        u64 C11 = f2sub(f2mul(X00, X22), f2mul(X02, X20));
        u64 C12 = f2sub(f2mul(X01, X20), f2mul(X00, X21));
        u64 C20 = f2sub(f2mul(X01, X12), f2mul(X02, X11));
        u64 C21 = f2sub(f2mul(X02, X10), f2mul(X00, X12));
        u64 C22 = f2sub(f2mul(X00, X11), f2mul(X01, X10));

        u64 det2 = f2fma(X00, C00, f2fma(X01, C01, f2mul(X02, C02)));
        float dA, dB; upk(det2, dA, dB);
        dA = (fabsf(dA) < 1e-30f) ? ((dA < 0.0f) ? -1e-30f : 1e-30f) : dA;
        dB = (fabsf(dB) < 1e-30f) ? ((dB < 0.0f) ? -1e-30f : 1e-30f) : dB;
        const float rdA = frcp_a(dA), rdB = frcp_a(dB);

        float caA, caB, cbA, cbB;
        if (it < 2) {
            u64 a2 = f2mul(X00, X00);
            a2 = f2fma(X01, X01, a2); a2 = f2fma(X02, X02, a2);
            a2 = f2fma(X10, X10, a2); a2 = f2fma(X11, X11, a2);
            a2 = f2fma(X12, X12, a2); a2 = f2fma(X20, X20, a2);
            a2 = f2fma(X21, X21, a2); a2 = f2fma(X22, X22, a2);
            u64 c2 = f2mul(C00, C00);
            c2 = f2fma(C01, C01, c2); c2 = f2fma(C02, C02, c2);
            c2 = f2fma(C10, C10, c2); c2 = f2fma(C11, C11, c2);
            c2 = f2fma(C12, C12, c2); c2 = f2fma(C20, C20, c2);
            c2 = f2fma(C21, C21, c2); c2 = f2fma(C22, C22, c2);
            float a2A, a2B, c2A, c2B; upk(a2, a2A, a2B); upk(c2, c2A, c2B);
            float rA = c2A * rdA * rdA * frcp_a(a2A);
            float rB = c2B * rdB * rdB * frcp_a(a2B);
            float tA = fsqrt_a(rA), tB = fsqrt_a(rB);
            caA = 0.5f * fsqrt_a(tA);  caB = 0.5f * fsqrt_a(tB);
            cbA = 0.5f * frsqrt_a(tA) * rdA;
            cbB = 0.5f * frsqrt_a(tB) * rdB;
        } else {
            caA = 0.5f; caB = 0.5f;
            cbA = 0.5f * rdA; cbB = 0.5f * rdB;
        }
        const u64 ca2 = pk(caA, caB), cb2 = pk(cbA, cbB);

        X00 = f2fma(ca2, X00, f2mul(cb2, C00));
        X01 = f2fma(ca2, X01, f2mul(cb2, C01));
        X02 = f2fma(ca2, X02, f2mul(cb2, C02));
        X10 = f2fma(ca2, X10, f2mul(cb2, C10));
        X11 = f2fma(ca2, X11, f2mul(cb2, C11));
        X12 = f2fma(ca2, X12, f2mul(cb2, C12));
        X20 = f2fma(ca2, X20, f2mul(cb2, C20));
        X21 = f2fma(ca2, X21, f2mul(cb2, C21));
        X22 = f2fma(ca2, X22, f2mul(cb2, C22));
    }

    // ---------------- Dp = R^T M R (packed) ----------------------------------
    u64 A00 = f2fma(M00, X00, f2fma(M01, X10, f2mul(M02, X20)));
    u64 A01 = f2fma(M00, X01, f2fma(M01, X11, f2mul(M02, X21)));
    u64 A02 = f2fma(M00, X02, f2fma(M01, X12, f2mul(M02, X22)));
    u64 A10 = f2fma(M01, X00, f2fma(M11, X10, f2mul(M12, X20)));
    u64 A11 = f2fma(M01, X01, f2fma(M11, X11, f2mul(M12, X21)));
    u64 A12 = f2fma(M01, X02, f2fma(M11, X12, f2mul(M12, X22)));
    u64 A20 = f2fma(M02, X00, f2fma(M12, X10, f2mul(M22, X20)));
    u64 A21 = f2fma(M02, X01, f2fma(M12, X11, f2mul(M22, X21)));
    u64 A22 = f2fma(M02, X02, f2fma(M12, X12, f2mul(M22, X22)));

    u64 Dp00 = f2fma(X00, A00, f2fma(X10, A10, f2mul(X20, A20)));
    u64 Dp10 = f2fma(X01, A00, f2fma(X11, A10, f2mul(X21, A20)));
    u64 Dp11 = f2fma(X01, A01, f2fma(X11, A11, f2mul(X21, A21)));
    u64 Dp20 = f2fma(X02, A00, f2fma(X12, A10, f2mul(X22, A20)));
    u64 Dp21 = f2fma(X02, A01, f2fma(X12, A11, f2mul(X22, A21)));
    u64 Dp22 = f2fma(X02, A02, f2fma(X12, A12, f2mul(X22, A22)));

    // packed lane order (lo=v, hi=v+1) matches memory order -> STG.64
    *(u64*)(out + v)          = Dp00;
    *(u64*)(out + NV + v)     = Dp10;
    *(u64*)(out + 2 * NV + v) = Dp11;
    *(u64*)(out + 3 * NV + v) = Dp20;
    *(u64*)(out + 4 * NV + v) = Dp21;
    *(u64*)(out + 5 * NV + v) = Dp22;
}

extern "C" void kernel_launch(void* const* d_in, const int* in_sizes, int n_in,
                              void* d_out, int out_size)
{
    const float* dti = (const float*)d_in[0];   // 6*128^3
    const float* ddf = (const float*)d_in[1];   // 3*128^3
    float* out = (float*)d_out;                 // 6*128^3
    (void)in_sizes; (void)n_in; (void)out_size;

    convert_kernel<<<NV / 4 / 256, 256>>>((const float4*)dti);
    warp_dti_kernel<<<NV / 2 / 256, 256>>>(ddf, out);
}

// round 13
// speedup vs baseline: 1.0004x; 1.0004x over previous
#include <cuda_runtime.h>
#include <cuda_fp16.h>

// Problem: B=1, H=W=D=128.
// dti: (6,128,128,128) f32 ; ddf: (3,128,128,128) f32 ; out: (6,128,128,128) f32
#define NV (128*128*128)

// fp16 interleaved gather array, padded to 16B/voxel (32MB):
//   g_t[v] = { h(c0,c1), h(c2,c3), h(c4,c5), 0 }
__device__ uint4 g_t[NV];

typedef unsigned long long u64;

__device__ __forceinline__ float frcp_a(float x)  { float r; asm("rcp.approx.f32 %0, %1;"   : "=f"(r) : "f"(x)); return r; }
__device__ __forceinline__ float fsqrt_a(float x) { float r; asm("sqrt.approx.f32 %0, %1;"  : "=f"(r) : "f"(x)); return r; }
__device__ __forceinline__ float frsqrt_a(float x){ float r; asm("rsqrt.approx.f32 %0, %1;" : "=f"(r) : "f"(x)); return r; }

// ---- packed f32x2 helpers (lane0 = low 32 bits = voxel A) ----
__device__ __forceinline__ u64 pk(float lo, float hi) {
    u64 r; asm("mov.b64 %0, {%1,%2};" : "=l"(r) : "f"(lo), "f"(hi)); return r;
}
__device__ __forceinline__ void upk(u64 v, float& lo, float& hi) {
    asm("mov.b64 {%0,%1}, %2;" : "=f"(lo), "=f"(hi) : "l"(v));
}
__device__ __forceinline__ u64 f2mul(u64 a, u64 b) {
    u64 r; asm("mul.rn.f32x2 %0, %1, %2;" : "=l"(r) : "l"(a), "l"(b)); return r;
}
__device__ __forceinline__ u64 f2add(u64 a, u64 b) {
    u64 r; asm("add.rn.f32x2 %0, %1, %2;" : "=l"(r) : "l"(a), "l"(b)); return r;
}
__device__ __forceinline__ u64 f2fma(u64 a, u64 b, u64 c) {
    u64 r; asm("fma.rn.f32x2 %0, %1, %2, %3;" : "=l"(r) : "l"(a), "l"(b), "l"(c)); return r;
}
#define KNEG1 0xBF800000BF800000ULL
#define KONE  0x3F8000003F800000ULL
__device__ __forceinline__ u64 f2sub(u64 a, u64 b) { return f2fma(b, (u64)KNEG1, a); }

__device__ __forceinline__ unsigned pack2h(float a, float b) {
    __half2 h = __floats2half2_rn(a, b);
    return *(unsigned*)&h;
}

// -------- pre-pass: planar fp32 (6,NV) -> interleaved fp16 uint4 (NV) -------
// 4 voxels per thread: 6x LDG.128 in, 4x STG.128 out, fully coalesced.
__global__ __launch_bounds__(256)
void convert_kernel(const float4* __restrict__ src4)
{
    const int j = blockIdx.x * 256 + threadIdx.x;    // [0, NV/4)
    const int Q = NV / 4;
    float4 c0 = src4[j];
    float4 c1 = src4[Q + j];
    float4 c2 = src4[2 * Q + j];
    float4 c3 = src4[3 * Q + j];
    float4 c4 = src4[4 * Q + j];
    float4 c5 = src4[5 * Q + j];
    uint4 t0, t1, t2, t3;
    t0.x = pack2h(c0.x, c1.x); t0.y = pack2h(c2.x, c3.x); t0.z = pack2h(c4.x, c5.x); t0.w = 0;
    t1.x = pack2h(c0.y, c1.y); t1.y = pack2h(c2.y, c3.y); t1.z = pack2h(c4.y, c5.y); t1.w = 0;
    t2.x = pack2h(c0.z, c1.z); t2.y = pack2h(c2.z, c3.z); t2.z = pack2h(c4.z, c5.z); t2.w = 0;
    t3.x = pack2h(c0.w, c1.w); t3.y = pack2h(c2.w, c3.w); t3.z = pack2h(c4.w, c5.w); t3.w = 0;
    g_t[4 * j]     = t0;
    g_t[4 * j + 1] = t1;
    g_t[4 * j + 2] = t2;
    g_t[4 * j + 3] = t3;
}

// corner-setup result for one voxel
struct GSetup {
    int i000, edx, edy, edz;
    float w[4];
    __half2 fzh;
};

__device__ __forceinline__ GSetup gsetup(float cxv, float cyv, float czv)
{
    GSetup s;
    float x0f = floorf(cxv), y0f = floorf(cyv), z0f = floorf(czv);
    float fx = cxv - x0f, fy = cyv - y0f, fz = czv - z0f;
    int x0 = (int)x0f, y0 = (int)y0f, z0 = (int)z0f;
    s.edx = (x0 < 127 ? 1 : 0) << 14;
    s.edy = (y0 < 127 ? 1 : 0) << 7;
    s.edz = (z0 < 127 ? 1 : 0);
    s.i000 = (x0 << 14) | (y0 << 7) | z0;
    s.fzh = __float2half2_rn(fz);
    const float gx0 = 1.0f - fx, gy0 = 1.0f - fy;
    s.w[0] = gx0 * gy0; s.w[1] = gx0 * fy; s.w[2] = fx * gy0; s.w[3] = fx * fy;
    return s;
}

__global__ __launch_bounds__(256, 4)
void warp_dti_kernel(const float* __restrict__ ddf,
                     float* __restrict__ out)
{
    const int t = blockIdx.x * 256 + threadIdx.x;   // NV/2 threads
    const int v = t << 1;                           // voxel pair (v, v+1)
    const int z = v & 127;                          // even, 0..126
    const int y = (v >> 7) & 127;
    const int x = v >> 14;

    // ---------------- center ddf for both voxels (packed LDG.64) ------------
    const u64 d0 = *(const u64*)(ddf + v);
    const u64 d1 = *(const u64*)(ddf + NV + v);
    const u64 d2 = *(const u64*)(ddf + 2 * NV + v);
    float dxA, dxB, dyA, dyB, dzA, dzB;
    upk(d0, dxA, dxB); upk(d1, dyA, dyB); upk(d2, dzA, dzB);

    // ---------------- trilinear gather, both voxels interleaved -------------
    GSetup sA = gsetup(fminf(fmaxf((float)x + dxA, 0.0f), 127.0f),
                       fminf(fmaxf((float)y + dyA, 0.0f), 127.0f),
                       fminf(fmaxf((float)z + dzA, 0.0f), 127.0f));
    GSetup sB = gsetup(fminf(fmaxf((float)x + dxB, 0.0f), 127.0f),
                       fminf(fmaxf((float)y + dyB, 0.0f), 127.0f),
                       fminf(fmaxf((float)(z + 1) + dzB, 0.0f), 127.0f));

    u64 a01 = 0, a23 = 0, a45 = 0;       // voxel A accumulators (channel pairs)
    u64 b01 = 0, b23 = 0, b45 = 0;       // voxel B
    #pragma unroll
    for (int k = 0; k < 4; k++) {
        const int iA = sA.i000 + ((k & 1) ? sA.edy : 0) + ((k & 2) ? sA.edx : 0);
        const int iB = sB.i000 + ((k & 1) ? sB.edy : 0) + ((k & 2) ? sB.edx : 0);
        // 4 independent LDG.128s
        const uint4 A0 = g_t[iA];
        const uint4 A1 = g_t[iA + sA.edz];
        const uint4 B0 = g_t[iB];
        const uint4 B1 = g_t[iB + sB.edz];

        const u64 wA = pk(sA.w[k], sA.w[k]);
        const u64 wB = pk(sB.w[k], sB.w[k]);

        __half2 p0 = *(const __half2*)&A0.x, q0 = *(const __half2*)&A1.x;
        __half2 p1 = *(const __half2*)&A0.y, q1 = *(const __half2*)&A1.y;
        __half2 p2 = *(const __half2*)&A0.z, q2 = *(const __half2*)&A1.z;
        float2 lA0 = __half22float2(__hfma2(sA.fzh, __hsub2(q0, p0), p0));
        float2 lA1 = __half22float2(__hfma2(sA.fzh, __hsub2(q1, p1), p1));
        float2 lA2 = __half22float2(__hfma2(sA.fzh, __hsub2(q2, p2), p2));
        a01 = f2fma(wA, pk(lA0.x, lA0.y), a01);
        a23 = f2fma(wA, pk(lA1.x, lA1.y), a23);
        a45 = f2fma(wA, pk(lA2.x, lA2.y), a45);

        __half2 r0 = *(const __half2*)&B0.x, s0 = *(const __half2*)&B1.x;
        __half2 r1 = *(const __half2*)&B0.y, s1 = *(const __half2*)&B1.y;
        __half2 r2 = *(const __half2*)&B0.z, s2 = *(const __half2*)&B1.z;
        float2 lB0 = __half22float2(__hfma2(sB.fzh, __hsub2(s0, r0), r0));
        float2 lB1 = __half22float2(__hfma2(sB.fzh, __hsub2(s1, r1), r1));
        float2 lB2 = __half22float2(__hfma2(sB.fzh, __hsub2(s2, r2), r2));
        b01 = f2fma(wB, pk(lB0.x, lB0.y), b01);
        b23 = f2fma(wB, pk(lB1.x, lB1.y), b23);
        b45 = f2fma(wB, pk(lB2.x, lB2.y), b45);
    }

    // repack channel-pairs -> voxel-pair M entries
    float m0A, m1A, m2A, m3A, m4A, m5A, m0B, m1B, m2B, m3B, m4B, m5B;
    upk(a01, m0A, m1A); upk(a23, m2A, m3A); upk(a45, m4A, m5A);
    upk(b01, m0B, m1B); upk(b23, m2B, m3B); upk(b45, m4B, m5B);
    const u64 M00 = pk(m0A, m0B), M01 = pk(m1A, m1B), M11 = pk(m2A, m2B);
    const u64 M02 = pk(m3A, m3B), M12 = pk(m4A, m4B), M22 = pk(m5A, m5B);

    // ---------------- Jacobian (packed over the voxel pair) -----------------
    const int xp = min(x + 1, 127), xm = max(x - 1, 0);
    const int yp = min(y + 1, 127), ym = max(y - 1, 0);
    const float sxs = 1.5f - 0.5f * (float)(xp - xm);
    const float sys = 1.5f - 0.5f * (float)(yp - ym);
    const float szA = (z == 0)   ? 1.0f : 0.5f;   // voxel A at z (z even)
    const float szB = (z == 126) ? 1.0f : 0.5f;   // voxel B at z+1
    const u64 sx2 = pk(sxs, sxs), sy2 = pk(sys, sys), sz2 = pk(szA, szB);

    const int rowb = (x << 14) | (y << 7);
    const int ixp = (xp << 14) | (y << 7) | z;
    const int ixm = (xm << 14) | (y << 7) | z;
    const int iyp = (x << 14) | (yp << 7) | z;
    const int iym = (x << 14) | (ym << 7) | z;
    const int izm = rowb + max(z - 1, 0);
    const int izp = rowb + min(z + 2, 127);

    u64 X00, X01, X02, X10, X11, X12, X20, X21, X22;
    {
        const u64 cen[3] = { d0, d1, d2 };
        u64 Xr[3][3];
        #pragma unroll
        for (int i = 0; i < 3; i++) {
            const float* p = ddf + i * NV;
            u64 pxp = *(const u64*)(p + ixp);
            u64 pxm = *(const u64*)(p + ixm);
            u64 pyp = *(const u64*)(p + iyp);
            u64 pym = *(const u64*)(p + iym);
            float pzm = p[izm], pzp = p[izp];
            float cl, ch; upk(cen[i], cl, ch);
            Xr[i][0] = f2mul(f2sub(pxp, pxm), sx2);
            Xr[i][1] = f2mul(f2sub(pyp, pym), sy2);
            Xr[i][2] = f2mul(f2sub(pk(ch, pzp), pk(pzm, cl)), sz2);
        }
        X00 = f2add(Xr[0][0], (u64)KONE); X01 = Xr[0][1]; X02 = Xr[0][2];
        X10 = Xr[1][0]; X11 = f2add(Xr[1][1], (u64)KONE); X12 = Xr[1][2];
        X20 = Xr[2][0]; X21 = Xr[2][1]; X22 = f2add(Xr[2][2], (u64)KONE);
    }

    // ---------------- polar factor: packed Newton (2 scaled + 2 plain) ------
    #pragma unroll
    for (int it = 0; it < 4; it++) {
        u64 C00 = f2sub(f2mul(X11, X22), f2mul(X12, X21));
        u64 C01 = f2sub(f2mul(X12, X20), f2mul(X10, X22));
        u64 C02 = f2sub(f2mul(X10, X21), f2mul(X11, X20));
        u64 C10 = f2sub(f2mul(X02, X21), f2mul(X01, X22));
        u64 C11 = f2sub(f2mul(X00, X22), f2mul(X02, X20));
        u64 C12 = f2sub(f2mul(X01, X20), f2mul(X00, X21));
        u64 C20 = f2sub(f2mul(X01, X12), f2mul(X02, X11));
        u64 C21 = f2sub(f2mul(X02, X10), f2mul(X00, X12));
        u64 C22 = f2sub(f2mul(X00, X11), f2mul(X01, X10));

        u64 det2 = f2fma(X00, C00, f2fma(X01, C01, f2mul(X02, C02)));
        float dA, dB; upk(det2, dA, dB);
        dA = (fabsf(dA) < 1e-30f) ? ((dA < 0.0f) ? -1e-30f : 1e-30f) : dA;
        dB = (fabsf(dB) < 1e-30f) ? ((dB < 0.0f) ? -1e-30f : 1e-30f) : dB;
        const float rdA = frcp_a(dA), rdB = frcp_a(dB);

        float caA, caB, cbA, cbB;
        if (it < 2) {
            u64 a2 = f2mul(X00, X00);
            a2 = f2fma(X01, X01, a2); a2 = f2fma(X02, X02, a2);
            a2 = f2fma(X10, X10, a2); a2 = f2fma(X11, X11, a2);
            a2 = f2fma(X12, X12, a2); a2 = f2fma(X20, X20, a2);
            a2 = f2fma(X21, X21, a2); a2 = f2fma(X22, X22, a2);
            u64 c2 = f2mul(C00, C00);
            c2 = f2fma(C01, C01, c2); c2 = f2fma(C02, C02, c2);
            c2 = f2fma(C10, C10, c2); c2 = f2fma(C11, C11, c2);
            c2 = f2fma(C12, C12, c2); c2 = f2fma(C20, C20, c2);
            c2 = f2fma(C21, C21, c2); c2 = f2fma(C22, C22, c2);
            float a2A, a2B, c2A, c2B; upk(a2, a2A, a2B); upk(c2, c2A, c2B);
            float rA = c2A * rdA * rdA * frcp_a(a2A);
            float rB = c2B * rdB * rdB * frcp_a(a2B);
            float tA = fsqrt_a(rA), tB = fsqrt_a(rB);
            caA = 0.5f * fsqrt_a(tA);  caB = 0.5f * fsqrt_a(tB);
            cbA = 0.5f * frsqrt_a(tA) * rdA;
            cbB = 0.5f * frsqrt_a(tB) * rdB;
        } else {
            caA = 0.5f; caB = 0.5f;
            cbA = 0.5f * rdA; cbB = 0.5f * rdB;
        }
        const u64 ca2 = pk(caA, caB), cb2 = pk(cbA, cbB);

        X00 = f2fma(ca2, X00, f2mul(cb2, C00));
        X01 = f2fma(ca2, X01, f2mul(cb2, C01));
        X02 = f2fma(ca2, X02, f2mul(cb2, C02));
        X10 = f2fma(ca2, X10, f2mul(cb2, C10));
        X11 = f2fma(ca2, X11, f2mul(cb2, C11));
        X12 = f2fma(ca2, X12, f2mul(cb2, C12));
        X20 = f2fma(ca2, X20, f2mul(cb2, C20));
        X21 = f2fma(ca2, X21, f2mul(cb2, C21));
        X22 = f2fma(ca2, X22, f2mul(cb2, C22));
    }

    // ---------------- Dp = R^T M R (packed) ----------------------------------
    u64 A00 = f2fma(M00, X00, f2fma(M01, X10, f2mul(M02, X20)));
    u64 A01 = f2fma(M00, X01, f2fma(M01, X11, f2mul(M02, X21)));
    u64 A02 = f2fma(M00, X02, f2fma(M01, X12, f2mul(M02, X22)));
    u64 A10 = f2fma(M01, X00, f2fma(M11, X10, f2mul(M12, X20)));
    u64 A11 = f2fma(M01, X01, f2fma(M11, X11, f2mul(M12, X21)));
    u64 A12 = f2fma(M01, X02, f2fma(M11, X12, f2mul(M12, X22)));
    u64 A20 = f2fma(M02, X00, f2fma(M12, X10, f2mul(M22, X20)));
    u64 A21 = f2fma(M02, X01, f2fma(M12, X11, f2mul(M22, X21)));
    u64 A22 = f2fma(M02, X02, f2fma(M12, X12, f2mul(M22, X22)));

    u64 Dp00 = f2fma(X00, A00, f2fma(X10, A10, f2mul(X20, A20)));
    u64 Dp10 = f2fma(X01, A00, f2fma(X11, A10, f2mul(X21, A20)));
    u64 Dp11 = f2fma(X01, A01, f2fma(X11, A11, f2mul(X21, A21)));
    u64 Dp20 = f2fma(X02, A00, f2fma(X12, A10, f2mul(X22, A20)));
    u64 Dp21 = f2fma(X02, A01, f2fma(X12, A11, f2mul(X22, A21)));
    u64 Dp22 = f2fma(X02, A02, f2fma(X12, A12, f2mul(X22, A22)));

    // packed lane order (lo=v, hi=v+1) matches memory order -> STG.64
    *(u64*)(out + v)          = Dp00;
    *(u64*)(out + NV + v)     = Dp10;
    *(u64*)(out + 2 * NV + v) = Dp11;
    *(u64*)(out + 3 * NV + v) = Dp20;
    *(u64*)(out + 4 * NV + v) = Dp21;
    *(u64*)(out + 5 * NV + v) = Dp22;
}

extern "C" void kernel_launch(void* const* d_in, const int* in_sizes, int n_in,
                              void* d_out, int out_size)
{
    const float* dti = (const float*)d_in[0];   // 6*128^3
    const float* ddf = (const float*)d_in[1];   // 3*128^3
    float* out = (float*)d_out;                 // 6*128^3
    (void)in_sizes; (void)n_in; (void)out_size;

    convert_kernel<<<NV / 4 / 256, 256>>>((const float4*)dti);
    warp_dti_kernel<<<NV / 2 / 256, 256>>>(ddf, out);
}